// round 10
// baseline (speedup 1.0000x reference)
#include <cuda_runtime.h>
#include <cuda_bf16.h>
#include <cstdint>

// ============================ helpers ============================
__device__ __forceinline__ uint32_t smem_u32(const void* p) {
    uint32_t a;
    asm("{ .reg .u64 t; cvta.to.shared.u64 t, %1; cvt.u32.u64 %0, t; }"
        : "=r"(a) : "l"(p));
    return a;
}

__device__ __forceinline__ void ldsm_x4(uint32_t* r, uint32_t addr) {
    asm volatile("ldmatrix.sync.aligned.m8n8.x4.shared.b16 {%0,%1,%2,%3}, [%4];"
                 : "=r"(r[0]), "=r"(r[1]), "=r"(r[2]), "=r"(r[3]) : "r"(addr));
}

__device__ __forceinline__ void mma_bf16(float* c, const uint32_t* a, const uint32_t* b) {
    asm volatile(
        "mma.sync.aligned.m16n8k16.row.col.f32.bf16.bf16.f32 "
        "{%0,%1,%2,%3}, {%4,%5,%6,%7}, {%8,%9}, {%0,%1,%2,%3};"
        : "+f"(c[0]), "+f"(c[1]), "+f"(c[2]), "+f"(c[3])
        : "r"(a[0]), "r"(a[1]), "r"(a[2]), "r"(a[3]), "r"(b[0]), "r"(b[1]));
}

// fp32 -> bf16 hi + bf16 lo (residual)
__device__ __forceinline__ void f2hl(float v, unsigned short& h, unsigned short& l) {
    __nv_bfloat16 hb = __float2bfloat16(v);
    float r = v - __bfloat162float(hb);
    h = __bfloat16_as_ushort(hb);
    l = __bfloat16_as_ushort(__float2bfloat16(r));
}

// ============================ global scratch ============================
#define NSPLIT 8
__device__ __align__(16) float g_part[NSPLIT][4096][64];   // split-K partials (8 MB)
__device__ __align__(16) __nv_bfloat16 g_thi[4096 * 64];   // t hi
__device__ __align__(16) __nv_bfloat16 g_tlo[4096 * 64];   // t lo
__device__ float g_norm[4096];                             // row norms

// ---------------- proj smem layout (K=128 slice, one-shot) ----------------
// row stride 136 halves = 272 B (128 k + 8 pad) -> conflict-free ldmatrix
#define RS2  136
#define RSB2 272
#define PA_HI 0
#define PA_LO 17408
#define PB_HI 34816
#define PB_LO 52224
#define P_SMEM 69632

// ---------------- dist smem layout (K=64), row stride 72 halves ----------
#define RS 72
#define RSB 144
#define DA_HI 0
#define DA_LO 18432
#define DB_HI 36864
#define DB_LO 55296
#define D_NI  73728
#define D_NJ  74240
#define D_SMEM 74752

// ---------------------------------------------------------------------------
// Kernel 1: proj. grid (64 M-tiles, 8 K-splits) x 128 thr (4 warps).
// t_part[64 x 64] = x[64 x 128] @ p[128 x 64], bf16 hi/lo 3-pass mma.sync.
// Full K=128 slice staged once; warp tile m16 x n64.
// ---------------------------------------------------------------------------
__global__ __launch_bounds__(128) void proj_mma(const float* __restrict__ x,
                                                const float* __restrict__ p) {
    extern __shared__ __align__(16) unsigned char sm[];
    const uint32_t sb = smem_u32(sm);
    const int tid = threadIdx.x, lane = tid & 31, wm = tid >> 5;
    const int r0 = blockIdx.x * 64;
    const int k0g = blockIdx.y * 128;

    // ---- stage x [64 rows x 128 k] fp32 -> A hi/lo ----
    #pragma unroll
    for (int it = 0; it < 16; it++) {
        int idx = tid + 128 * it;          // float4 index
        int row = idx >> 5, q = idx & 31;  // 32 float4 per row
        float4 v = *(const float4*)&x[(size_t)(r0 + row) * 1024 + k0g + 4 * q];
        unsigned short h0, h1, h2, h3, l0, l1, l2, l3;
        f2hl(v.x, h0, l0); f2hl(v.y, h1, l1);
        f2hl(v.z, h2, l2); f2hl(v.w, h3, l3);
        uint2 hw, lw;
        hw.x = (uint32_t)h0 | ((uint32_t)h1 << 16);
        hw.y = (uint32_t)h2 | ((uint32_t)h3 << 16);
        lw.x = (uint32_t)l0 | ((uint32_t)l1 << 16);
        lw.y = (uint32_t)l2 | ((uint32_t)l3 << 16);
        uint32_t off = (uint32_t)row * RSB2 + (uint32_t)q * 8;
        *(uint2*)(sm + PA_HI + off) = hw;
        *(uint2*)(sm + PA_LO + off) = lw;
    }
    // ---- stage p [128 k x 64 j] -> B[j][k] hi/lo (transpose on store) ----
    #pragma unroll
    for (int it = 0; it < 16; it++) {
        int e = tid + 128 * it;            // float4 index into p slice
        int kk = e >> 4, jb = (e & 15) * 4;
        float4 v = *(const float4*)&p[(size_t)(k0g + kk) * 64 + jb];
        unsigned short h, l;
        uint32_t co = (uint32_t)kk * 2;
        f2hl(v.x, h, l);
        *(unsigned short*)(sm + PB_HI + (jb + 0) * RSB2 + co) = h;
        *(unsigned short*)(sm + PB_LO + (jb + 0) * RSB2 + co) = l;
        f2hl(v.y, h, l);
        *(unsigned short*)(sm + PB_HI + (jb + 1) * RSB2 + co) = h;
        *(unsigned short*)(sm + PB_LO + (jb + 1) * RSB2 + co) = l;
        f2hl(v.z, h, l);
        *(unsigned short*)(sm + PB_HI + (jb + 2) * RSB2 + co) = h;
        *(unsigned short*)(sm + PB_LO + (jb + 2) * RSB2 + co) = l;
        f2hl(v.w, h, l);
        *(unsigned short*)(sm + PB_HI + (jb + 3) * RSB2 + co) = h;
        *(unsigned short*)(sm + PB_LO + (jb + 3) * RSB2 + co) = l;
    }
    __syncthreads();

    float acc[8][4];
    #pragma unroll
    for (int j = 0; j < 8; j++)
        #pragma unroll
        for (int q = 0; q < 4; q++) acc[j][q] = 0.f;

    const uint32_t aoff[3] = {PA_HI, PA_HI, PA_LO};
    const uint32_t boff[3] = {PB_HI, PB_LO, PB_HI};

    #pragma unroll
    for (int ps = 0; ps < 3; ps++) {
        uint32_t abase = sb + aoff[ps] +
            (uint32_t)(wm * 16 + (lane & 15)) * RSB2 + (uint32_t)(lane >> 4) * 16;
        uint32_t bbase = sb + boff[ps] +
            (uint32_t)(((lane >> 4) << 3) + (lane & 7)) * RSB2 +
            (uint32_t)((lane >> 3) & 1) * 16;
        #pragma unroll
        for (int ks = 0; ks < 8; ks++) {
            uint32_t a0[4];
            ldsm_x4(a0, abase + ks * 32);
            #pragma unroll
            for (int np = 0; np < 4; np++) {
                uint32_t bf[4];
                ldsm_x4(bf, bbase + np * 16 * RSB2 + ks * 32);
                mma_bf16(acc[2 * np], a0, bf);
                mma_bf16(acc[2 * np + 1], a0, bf + 2);
            }
        }
    }

    // epilogue: write fp32 partials
    const int ks = blockIdx.y;
    int rowa = r0 + wm * 16 + (lane >> 2);
    #pragma unroll
    for (int nt = 0; nt < 8; nt++) {
        int col = nt * 8 + (lane & 3) * 2;
        float2 v0 = {acc[nt][0], acc[nt][1]};
        float2 v1 = {acc[nt][2], acc[nt][3]};
        *(float2*)&g_part[ks][rowa][col] = v0;
        *(float2*)&g_part[ks][rowa + 8][col] = v1;
    }
}

// ---------------------------------------------------------------------------
// Kernel 2: reduce NSPLIT partials -> norms + bf16 hi/lo.
// grid 64 x 256; one thread per (row, 16-col group). Norm via shfl over the
// 4 threads sharing a row (lane groups of 4).
// ---------------------------------------------------------------------------
__global__ __launch_bounds__(256) void convert_t() {
    int gid = blockIdx.x * 256 + threadIdx.x;
    int row = gid >> 2;
    int cg = (gid & 3) * 16;   // column base

    float t[16];
    #pragma unroll
    for (int q = 0; q < 4; q++) { t[4*q] = 0.f; t[4*q+1] = 0.f; t[4*q+2] = 0.f; t[4*q+3] = 0.f; }
    #pragma unroll
    for (int s = 0; s < NSPLIT; s++) {
        #pragma unroll
        for (int q = 0; q < 4; q++) {
            float4 v = *(const float4*)&g_part[s][row][cg + 4 * q];
            t[4*q] += v.x; t[4*q+1] += v.y; t[4*q+2] += v.z; t[4*q+3] += v.w;
        }
    }
    float nm = 0.f;
    #pragma unroll
    for (int k = 0; k < 16; k++) nm += t[k] * t[k];
    nm += __shfl_xor_sync(0xFFFFFFFF, nm, 1);
    nm += __shfl_xor_sync(0xFFFFFFFF, nm, 2);
    if ((gid & 3) == 0) g_norm[row] = nm;

    #pragma unroll
    for (int q = 0; q < 2; q++) {   // two uint4 (8 halves each) per array
        unsigned short h[8], l[8];
        #pragma unroll
        for (int d = 0; d < 8; d++) f2hl(t[8 * q + d], h[d], l[d]);
        uint4 hw, lw;
        hw.x = (uint32_t)h[0] | ((uint32_t)h[1] << 16);
        hw.y = (uint32_t)h[2] | ((uint32_t)h[3] << 16);
        hw.z = (uint32_t)h[4] | ((uint32_t)h[5] << 16);
        hw.w = (uint32_t)h[6] | ((uint32_t)h[7] << 16);
        lw.x = (uint32_t)l[0] | ((uint32_t)l[1] << 16);
        lw.y = (uint32_t)l[2] | ((uint32_t)l[3] << 16);
        lw.z = (uint32_t)l[4] | ((uint32_t)l[5] << 16);
        lw.w = (uint32_t)l[6] | ((uint32_t)l[7] << 16);
        *(uint4*)&g_thi[(size_t)row * 64 + cg + 8 * q] = hw;
        *(uint4*)&g_tlo[(size_t)row * 64 + cg + 8 * q] = lw;
    }
}

// ---------------------------------------------------------------------------
// Kernel 3: dist. grid (8 j, 8 i, 4 b) x 256 thr. Block 128i x 128j, K=64.
// G via 3-pass bf16 mma.sync; out = ni + nj - 2G fused in the epilogue.
// Warp tile 32m x 64n (8 warps as 4x2).
// ---------------------------------------------------------------------------
__global__ __launch_bounds__(256) void dist_mma(float* __restrict__ out) {
    extern __shared__ __align__(16) unsigned char sm[];
    const uint32_t sb = smem_u32(sm);
    const int tid = threadIdx.x, lane = tid & 31, wid = tid >> 5;
    const int b = blockIdx.z;
    const int i0 = blockIdx.y * 128;
    const int j0 = blockIdx.x * 128;
    const int wm = wid & 3, wn = wid >> 2;

    const __nv_bfloat16* sih = g_thi + (size_t)(b * 1024 + i0) * 64;
    const __nv_bfloat16* sil = g_tlo + (size_t)(b * 1024 + i0) * 64;
    const __nv_bfloat16* sjh = g_thi + (size_t)(b * 1024 + j0) * 64;
    const __nv_bfloat16* sjl = g_tlo + (size_t)(b * 1024 + j0) * 64;
    #pragma unroll
    for (int it = 0; it < 4; it++) {
        int idx = tid + 256 * it;
        int row = idx >> 3, q = idx & 7;
        uint32_t off = (uint32_t)row * RSB + (uint32_t)q * 16;
        size_t e = (size_t)row * 64 + q * 8;
        *(uint4*)(sm + DA_HI + off) = *(const uint4*)(sih + e);
        *(uint4*)(sm + DA_LO + off) = *(const uint4*)(sil + e);
        *(uint4*)(sm + DB_HI + off) = *(const uint4*)(sjh + e);
        *(uint4*)(sm + DB_LO + off) = *(const uint4*)(sjl + e);
    }
    if (tid < 128)
        ((float*)(sm + D_NI))[tid] = g_norm[b * 1024 + i0 + tid];
    else
        ((float*)(sm + D_NJ))[tid - 128] = g_norm[b * 1024 + j0 + tid - 128];
    __syncthreads();

    float acc[2][8][4];
    #pragma unroll
    for (int i = 0; i < 2; i++)
        #pragma unroll
        for (int j = 0; j < 8; j++)
            #pragma unroll
            for (int q = 0; q < 4; q++) acc[i][j][q] = 0.f;

    const uint32_t aoff[3] = {DA_HI, DA_HI, DA_LO};
    const uint32_t boff[3] = {DB_HI, DB_LO, DB_HI};

    #pragma unroll
    for (int ps = 0; ps < 3; ps++) {
        uint32_t abase = sb + aoff[ps] +
            (uint32_t)(wm * 32 + (lane & 15)) * RSB + (uint32_t)(lane >> 4) * 16;
        uint32_t bbase = sb + boff[ps] +
            (uint32_t)(wn * 64 + ((lane >> 4) << 3) + (lane & 7)) * RSB +
            (uint32_t)((lane >> 3) & 1) * 16;
        #pragma unroll
        for (int ks = 0; ks < 4; ks++) {
            uint32_t a0[4], a1[4];
            ldsm_x4(a0, abase + ks * 32);
            ldsm_x4(a1, abase + 16 * RSB + ks * 32);
            #pragma unroll
            for (int np = 0; np < 4; np++) {
                uint32_t bf[4];
                ldsm_x4(bf, bbase + np * 16 * RSB + ks * 32);
                mma_bf16(acc[0][2 * np], a0, bf);
                mma_bf16(acc[0][2 * np + 1], a0, bf + 2);
                mma_bf16(acc[1][2 * np], a1, bf);
                mma_bf16(acc[1][2 * np + 1], a1, bf + 2);
            }
        }
    }

    const float* ni_s = (const float*)(sm + D_NI);
    const float* nj_s = (const float*)(sm + D_NJ);
    const bool diag = (i0 == j0);
    #pragma unroll
    for (int mi = 0; mi < 2; mi++) {
        int lr0 = wm * 32 + mi * 16 + (lane >> 2);
        int lr1 = lr0 + 8;
        float n0 = ni_s[lr0], n1 = ni_s[lr1];
        float* ob0 = out + ((size_t)(b * 1024 + i0 + lr0)) * 1024 + j0;
        float* ob1 = out + ((size_t)(b * 1024 + i0 + lr1)) * 1024 + j0;
        #pragma unroll
        for (int nt = 0; nt < 8; nt++) {
            int lc = wn * 64 + nt * 8 + (lane & 3) * 2;
            float njA = nj_s[lc], njB = nj_s[lc + 1];
            float2 v0, v1;
            v0.x = n0 + njA - 2.f * acc[mi][nt][0];
            v0.y = n0 + njB - 2.f * acc[mi][nt][1];
            v1.x = n1 + njA - 2.f * acc[mi][nt][2];
            v1.y = n1 + njB - 2.f * acc[mi][nt][3];
            if (diag) {
                if (lr0 == lc)     v0.x = 0.f;
                if (lr0 == lc + 1) v0.y = 0.f;
                if (lr1 == lc)     v1.x = 0.f;
                if (lr1 == lc + 1) v1.y = 0.f;
            }
            *(float2*)&ob0[lc] = v0;
            *(float2*)&ob1[lc] = v1;
        }
    }
}

// ============================ launch ============================
extern "C" void kernel_launch(void* const* d_in, const int* in_sizes, int n_in,
                              void* d_out, int out_size) {
    const float* x = (const float*)d_in[0];   // [4, 1024, 1024] fp32
    const float* p = (const float*)d_in[1];   // [1024, 64] fp32
    float* out = (float*)d_out;               // [4, 1024, 1024] fp32

    static bool attr_done = false;
    if (!attr_done) {
        cudaFuncSetAttribute(proj_mma, cudaFuncAttributeMaxDynamicSharedMemorySize, P_SMEM);
        cudaFuncSetAttribute(dist_mma, cudaFuncAttributeMaxDynamicSharedMemorySize, D_SMEM);
        attr_done = true;
    }

    proj_mma<<<dim3(64, NSPLIT), 128, P_SMEM>>>(x, p);
    convert_t<<<64, 256>>>();
    dist_mma<<<dim3(8, 8, 4), 256, D_SMEM>>>(out);
}

// round 17
// speedup vs baseline: 1.1953x; 1.1953x over previous
#include <cuda_runtime.h>
#include <cuda_bf16.h>
#include <cstdint>

// ============================ helpers ============================
__device__ __forceinline__ uint32_t smem_u32(const void* p) {
    uint32_t a;
    asm("{ .reg .u64 t; cvta.to.shared.u64 t, %1; cvt.u32.u64 %0, t; }"
        : "=r"(a) : "l"(p));
    return a;
}

__device__ __forceinline__ void ldsm_x4(uint32_t* r, uint32_t addr) {
    asm volatile("ldmatrix.sync.aligned.m8n8.x4.shared.b16 {%0,%1,%2,%3}, [%4];"
                 : "=r"(r[0]), "=r"(r[1]), "=r"(r[2]), "=r"(r[3]) : "r"(addr));
}

__device__ __forceinline__ void mma_bf16(float* c, const uint32_t* a, const uint32_t* b) {
    asm volatile(
        "mma.sync.aligned.m16n8k16.row.col.f32.bf16.bf16.f32 "
        "{%0,%1,%2,%3}, {%4,%5,%6,%7}, {%8,%9}, {%0,%1,%2,%3};"
        : "+f"(c[0]), "+f"(c[1]), "+f"(c[2]), "+f"(c[3])
        : "r"(a[0]), "r"(a[1]), "r"(a[2]), "r"(a[3]), "r"(b[0]), "r"(b[1]));
}

// fp32 -> bf16 hi + bf16 lo (residual)
__device__ __forceinline__ void f2hl(float v, unsigned short& h, unsigned short& l) {
    __nv_bfloat16 hb = __float2bfloat16(v);
    float r = v - __bfloat162float(hb);
    h = __bfloat16_as_ushort(hb);
    l = __bfloat16_as_ushort(__float2bfloat16(r));
}

// ============================ global scratch ============================
#define NSPLIT 8
__device__ __align__(16) float g_part[NSPLIT][4096][64];        // split-K partials (8 MB)
__device__ __align__(16) __nv_bfloat16 g_thi[4096 * 64];        // t hi
__device__ __align__(16) __nv_bfloat16 g_tlo[4096 * 64];        // t lo
__device__ float g_norm[4096];                                  // row norms
__device__ __align__(16) __nv_bfloat16 g_pT_hi[64 * 1024];      // p^T hi [j][k]
__device__ __align__(16) __nv_bfloat16 g_pT_lo[64 * 1024];      // p^T lo [j][k]

// ---------------- proj smem layout (K=128 slice, one-shot) ----------------
// row stride 136 halves = 272 B (128 k + 8 pad) -> conflict-free ldmatrix
#define RSB2 272
#define PA_HI 0
#define PA_LO 17408
#define PB_HI 34816
#define PB_LO 52224
#define P_SMEM 69632

// ---------------- dist smem layout (K=64), row stride 72 halves ----------
#define RSB 144
#define DA_HI 0
#define DA_LO 18432
#define DB_HI 36864
#define DB_LO 55296
#define D_NI  73728
#define D_NJ  74240
#define D_SMEM 74752

// ---------------------------------------------------------------------------
// Kernel 0: prep p -> transposed bf16 hi/lo [64 j][1024 k]. 16 blocks x 256.
// ---------------------------------------------------------------------------
__global__ __launch_bounds__(256) void prep_p(const float* __restrict__ p) {
    __shared__ unsigned short shh[64][72], shl[64][72];
    const int tid = threadIdx.x;
    const int k0 = blockIdx.x * 64;
    #pragma unroll
    for (int it = 0; it < 4; it++) {
        int fid = tid + 256 * it;           // float4 id within 64k x 64j tile
        int kk = fid >> 4, j4 = (fid & 15) * 4;
        float4 v = *(const float4*)&p[(size_t)(k0 + kk) * 64 + j4];
        unsigned short h, l;
        f2hl(v.x, h, l); shh[j4 + 0][kk] = h; shl[j4 + 0][kk] = l;
        f2hl(v.y, h, l); shh[j4 + 1][kk] = h; shl[j4 + 1][kk] = l;
        f2hl(v.z, h, l); shh[j4 + 2][kk] = h; shl[j4 + 2][kk] = l;
        f2hl(v.w, h, l); shh[j4 + 3][kk] = h; shl[j4 + 3][kk] = l;
    }
    __syncthreads();
    #pragma unroll
    for (int w = 0; w < 2; w++) {
        int idx = tid + 256 * w;            // uint4 id: 64 j x 8 q
        int j = idx >> 3, q = idx & 7;
        *(uint4*)&g_pT_hi[(size_t)j * 1024 + k0 + q * 8] = *(uint4*)&shh[j][q * 8];
        *(uint4*)&g_pT_lo[(size_t)j * 1024 + k0 + q * 8] = *(uint4*)&shl[j][q * 8];
    }
}

// ---------------------------------------------------------------------------
// Kernel 1: proj. grid (64 M-tiles, 8 K-splits) x 128 thr (4 warps).
// t_part[64 x 64] = x[64 x 128] @ p[128 x 64], bf16 hi/lo 3-pass mma.sync.
// Full K=128 slice staged once; warp tile m16 x n64.
// p staged as a clean vectorized copy from the prepped [j][k] arrays.
// ---------------------------------------------------------------------------
__global__ __launch_bounds__(128) void proj_mma(const float* __restrict__ x) {
    extern __shared__ __align__(16) unsigned char sm[];
    const uint32_t sb = smem_u32(sm);
    const int tid = threadIdx.x, lane = tid & 31, wm = tid >> 5;
    const int r0 = blockIdx.x * 64;
    const int k0 = blockIdx.y * 128;

    // ---- stage x [64 rows x 128 k] fp32 -> A hi/lo (vectorized, as in R10) ----
    #pragma unroll
    for (int it = 0; it < 16; it++) {
        int idx = tid + 128 * it;          // float4 index: 64 rows x 32 = 2048
        int row = idx >> 5, q = idx & 31;
        float4 v = *(const float4*)&x[(size_t)(r0 + row) * 1024 + k0 + 4 * q];
        unsigned short h0, h1, h2, h3, l0, l1, l2, l3;
        f2hl(v.x, h0, l0); f2hl(v.y, h1, l1);
        f2hl(v.z, h2, l2); f2hl(v.w, h3, l3);
        uint2 hw, lw;
        hw.x = (uint32_t)h0 | ((uint32_t)h1 << 16);
        hw.y = (uint32_t)h2 | ((uint32_t)h3 << 16);
        lw.x = (uint32_t)l0 | ((uint32_t)l1 << 16);
        lw.y = (uint32_t)l2 | ((uint32_t)l3 << 16);
        uint32_t off = (uint32_t)row * RSB2 + (uint32_t)q * 8;
        *(uint2*)(sm + PA_HI + off) = hw;
        *(uint2*)(sm + PA_LO + off) = lw;
    }
    // ---- stage p tiles: full 64 j x 16 uint4 (128 k halves) per array ----
    #pragma unroll
    for (int it = 0; it < 8; it++) {
        int idx = tid + 128 * it;          // 64 j x 16 uint4 = 1024
        int j = idx >> 4, q = idx & 15;
        uint32_t off = (uint32_t)j * RSB2 + (uint32_t)q * 16;
        size_t e = (size_t)j * 1024 + k0 + q * 8;
        *(uint4*)(sm + PB_HI + off) = *(const uint4*)&g_pT_hi[e];
        *(uint4*)(sm + PB_LO + off) = *(const uint4*)&g_pT_lo[e];
    }
    __syncthreads();

    float acc[8][4];
    #pragma unroll
    for (int j = 0; j < 8; j++)
        #pragma unroll
        for (int q = 0; q < 4; q++) acc[j][q] = 0.f;

    const uint32_t aoff[3] = {PA_HI, PA_HI, PA_LO};
    const uint32_t boff[3] = {PB_HI, PB_LO, PB_HI};

    #pragma unroll
    for (int ps = 0; ps < 3; ps++) {
        uint32_t abase = sb + aoff[ps] +
            (uint32_t)(wm * 16 + (lane & 15)) * RSB2 + (uint32_t)(lane >> 4) * 16;
        uint32_t bbase = sb + boff[ps] +
            (uint32_t)(((lane >> 4) << 3) + (lane & 7)) * RSB2 +
            (uint32_t)((lane >> 3) & 1) * 16;
        #pragma unroll
        for (int ks = 0; ks < 8; ks++) {
            uint32_t a0[4];
            ldsm_x4(a0, abase + ks * 32);
            #pragma unroll
            for (int np = 0; np < 4; np++) {
                uint32_t bf[4];
                ldsm_x4(bf, bbase + np * 16 * RSB2 + ks * 32);
                mma_bf16(acc[2 * np], a0, bf);
                mma_bf16(acc[2 * np + 1], a0, bf + 2);
            }
        }
    }

    // epilogue: write fp32 partials
    const int ks = blockIdx.y;
    int rowa = r0 + wm * 16 + (lane >> 2);
    #pragma unroll
    for (int nt = 0; nt < 8; nt++) {
        int col = nt * 8 + (lane & 3) * 2;
        float2 v0 = {acc[nt][0], acc[nt][1]};
        float2 v1 = {acc[nt][2], acc[nt][3]};
        *(float2*)&g_part[ks][rowa][col] = v0;
        *(float2*)&g_part[ks][rowa + 8][col] = v1;
    }
}

// ---------------------------------------------------------------------------
// Kernel 2: reduce NSPLIT partials -> norms + bf16 hi/lo. grid 64 x 256.
// (passed in R10)
// ---------------------------------------------------------------------------
__global__ __launch_bounds__(256) void convert_t() {
    int gid = blockIdx.x * 256 + threadIdx.x;
    int row = gid >> 2;
    int cg = (gid & 3) * 16;

    float t[16];
    #pragma unroll
    for (int k = 0; k < 16; k++) t[k] = 0.f;
    #pragma unroll
    for (int s = 0; s < NSPLIT; s++) {
        #pragma unroll
        for (int q = 0; q < 4; q++) {
            float4 v = *(const float4*)&g_part[s][row][cg + 4 * q];
            t[4*q] += v.x; t[4*q+1] += v.y; t[4*q+2] += v.z; t[4*q+3] += v.w;
        }
    }
    float nm = 0.f;
    #pragma unroll
    for (int k = 0; k < 16; k++) nm += t[k] * t[k];
    nm += __shfl_xor_sync(0xFFFFFFFF, nm, 1);
    nm += __shfl_xor_sync(0xFFFFFFFF, nm, 2);
    if ((gid & 3) == 0) g_norm[row] = nm;

    #pragma unroll
    for (int q = 0; q < 2; q++) {
        unsigned short h[8], l[8];
        #pragma unroll
        for (int d = 0; d < 8; d++) f2hl(t[8 * q + d], h[d], l[d]);
        uint4 hw, lw;
        hw.x = (uint32_t)h[0] | ((uint32_t)h[1] << 16);
        hw.y = (uint32_t)h[2] | ((uint32_t)h[3] << 16);
        hw.z = (uint32_t)h[4] | ((uint32_t)h[5] << 16);
        hw.w = (uint32_t)h[6] | ((uint32_t)h[7] << 16);
        lw.x = (uint32_t)l[0] | ((uint32_t)l[1] << 16);
        lw.y = (uint32_t)l[2] | ((uint32_t)l[3] << 16);
        lw.z = (uint32_t)l[4] | ((uint32_t)l[5] << 16);
        lw.w = (uint32_t)l[6] | ((uint32_t)l[7] << 16);
        *(uint4*)&g_thi[(size_t)row * 64 + cg + 8 * q] = hw;
        *(uint4*)&g_tlo[(size_t)row * 64 + cg + 8 * q] = lw;
    }
}

// ---------------------------------------------------------------------------
// Kernel 3: dist. grid (8 j, 8 i, 4 b) x 256 thr. Block 128i x 128j, K=64.
// (passed in R9/R10, verbatim) Warp tile 32m x 64n (8 warps as 4x2).
// ---------------------------------------------------------------------------
__global__ __launch_bounds__(256) void dist_mma(float* __restrict__ out) {
    extern __shared__ __align__(16) unsigned char sm[];
    const uint32_t sb = smem_u32(sm);
    const int tid = threadIdx.x, lane = tid & 31, wid = tid >> 5;
    const int b = blockIdx.z;
    const int i0 = blockIdx.y * 128;
    const int j0 = blockIdx.x * 128;
    const int wm = wid & 3, wn = wid >> 2;

    const __nv_bfloat16* sih = g_thi + (size_t)(b * 1024 + i0) * 64;
    const __nv_bfloat16* sil = g_tlo + (size_t)(b * 1024 + i0) * 64;
    const __nv_bfloat16* sjh = g_thi + (size_t)(b * 1024 + j0) * 64;
    const __nv_bfloat16* sjl = g_tlo + (size_t)(b * 1024 + j0) * 64;
    #pragma unroll
    for (int it = 0; it < 4; it++) {
        int idx = tid + 256 * it;
        int row = idx >> 3, q = idx & 7;
        uint32_t off = (uint32_t)row * RSB + (uint32_t)q * 16;
        size_t e = (size_t)row * 64 + q * 8;
        *(uint4*)(sm + DA_HI + off) = *(const uint4*)(sih + e);
        *(uint4*)(sm + DA_LO + off) = *(const uint4*)(sil + e);
        *(uint4*)(sm + DB_HI + off) = *(const uint4*)(sjh + e);
        *(uint4*)(sm + DB_LO + off) = *(const uint4*)(sjl + e);
    }
    if (tid < 128)
        ((float*)(sm + D_NI))[tid] = g_norm[b * 1024 + i0 + tid];
    else
        ((float*)(sm + D_NJ))[tid - 128] = g_norm[b * 1024 + j0 + tid - 128];
    __syncthreads();

    float acc[2][8][4];
    #pragma unroll
    for (int i = 0; i < 2; i++)
        #pragma unroll
        for (int j = 0; j < 8; j++)
            #pragma unroll
            for (int q = 0; q < 4; q++) acc[i][j][q] = 0.f;

    const uint32_t aoff[3] = {DA_HI, DA_HI, DA_LO};
    const uint32_t boff[3] = {DB_HI, DB_LO, DB_HI};

    #pragma unroll
    for (int ps = 0; ps < 3; ps++) {
        uint32_t abase = sb + aoff[ps] +
            (uint32_t)(wm * 32 + (lane & 15)) * RSB + (uint32_t)(lane >> 4) * 16;
        uint32_t bbase = sb + boff[ps] +
            (uint32_t)(wn * 64 + ((lane >> 4) << 3) + (lane & 7)) * RSB +
            (uint32_t)((lane >> 3) & 1) * 16;
        #pragma unroll
        for (int ks = 0; ks < 4; ks++) {
            uint32_t a0[4], a1[4];
            ldsm_x4(a0, abase + ks * 32);
            ldsm_x4(a1, abase + 16 * RSB + ks * 32);
            #pragma unroll
            for (int np = 0; np < 4; np++) {
                uint32_t bf[4];
                ldsm_x4(bf, bbase + np * 16 * RSB + ks * 32);
                mma_bf16(acc[0][2 * np], a0, bf);
                mma_bf16(acc[0][2 * np + 1], a0, bf + 2);
                mma_bf16(acc[1][2 * np], a1, bf);
                mma_bf16(acc[1][2 * np + 1], a1, bf + 2);
            }
        }
    }

    const float* ni_s = (const float*)(sm + D_NI);
    const float* nj_s = (const float*)(sm + D_NJ);
    const bool diag = (i0 == j0);
    #pragma unroll
    for (int mi = 0; mi < 2; mi++) {
        int lr0 = wm * 32 + mi * 16 + (lane >> 2);
        int lr1 = lr0 + 8;
        float n0 = ni_s[lr0], n1 = ni_s[lr1];
        float* ob0 = out + ((size_t)(b * 1024 + i0 + lr0)) * 1024 + j0;
        float* ob1 = out + ((size_t)(b * 1024 + i0 + lr1)) * 1024 + j0;
        #pragma unroll
        for (int nt = 0; nt < 8; nt++) {
            int lc = wn * 64 + nt * 8 + (lane & 3) * 2;
            float njA = nj_s[lc], njB = nj_s[lc + 1];
            float2 v0, v1;
            v0.x = n0 + njA - 2.f * acc[mi][nt][0];
            v0.y = n0 + njB - 2.f * acc[mi][nt][1];
            v1.x = n1 + njA - 2.f * acc[mi][nt][2];
            v1.y = n1 + njB - 2.f * acc[mi][nt][3];
            if (diag) {
                if (lr0 == lc)     v0.x = 0.f;
                if (lr0 == lc + 1) v0.y = 0.f;
                if (lr1 == lc)     v1.x = 0.f;
                if (lr1 == lc + 1) v1.y = 0.f;
            }
            *(float2*)&ob0[lc] = v0;
            *(float2*)&ob1[lc] = v1;
        }
    }
}

// ============================ launch ============================
extern "C" void kernel_launch(void* const* d_in, const int* in_sizes, int n_in,
                              void* d_out, int out_size) {
    const float* x = (const float*)d_in[0];   // [4, 1024, 1024] fp32
    const float* p = (const float*)d_in[1];   // [1024, 64] fp32
    float* out = (float*)d_out;               // [4, 1024, 1024] fp32

    static bool attr_done = false;
    if (!attr_done) {
        cudaFuncSetAttribute(proj_mma, cudaFuncAttributeMaxDynamicSharedMemorySize, P_SMEM);
        cudaFuncSetAttribute(dist_mma, cudaFuncAttributeMaxDynamicSharedMemorySize, D_SMEM);
        attr_done = true;
    }

    prep_p<<<16, 256>>>(p);
    proj_mma<<<dim3(64, NSPLIT), 128, P_SMEM>>>(x);
    convert_t<<<64, 256>>>();
    dist_mma<<<dim3(8, 8, 4), 256, D_SMEM>>>(out);
}